// round 7
// baseline (speedup 1.0000x reference)
#include <cuda_runtime.h>
#include <math.h>

// Problem constants
#define Bc   2
#define Ac   4
#define Cc   3
#define HWc  1024
#define Nc   4096              // H*W*A
#define LOG2E 1.4426950408889634f

// Scratch (device globals — no allocation allowed)
__device__ float4 g_box[Bc*Nc];   // BEV boxes (x1,y1,x2,y2)
__device__ float4 g_p1v[Bc*Nc];   // p1 per class in .x/.y/.z ; .w = box area
__device__ float4 g_smv[Bc*Nc];   // softmaxed score per class in .x/.y/.z
__device__ float4 g_p0s[Bc*Nc];   // p0*log2e per class in .x/.y/.z

__device__ __forceinline__ float ex2f(float x) {
    float y; asm("ex2.approx.f32 %0, %1;" : "=f"(y) : "f"(x)); return y;
}
__device__ __forceinline__ float warpMax(float v) {
    #pragma unroll
    for (int o = 16; o; o >>= 1) v = fmaxf(v, __shfl_xor_sync(0xffffffffu, v, o));
    return v;
}
__device__ __forceinline__ float warpSum(float v) {
    #pragma unroll
    for (int o = 16; o; o >>= 1) v += __shfl_xor_sync(0xffffffffu, v, o);
    return v;
}
__device__ float blockReduce(float v, bool isMax, float* sm) {
    int tid = threadIdx.x, lane = tid & 31, w = tid >> 5;
    v = isMax ? warpMax(v) : warpSum(v);
    __syncthreads();
    if (lane == 0) sm[w] = v;
    __syncthreads();
    if (tid == 0) {
        float r = sm[0];
        int nw = blockDim.x >> 5;
        for (int i = 1; i < nw; i++) r = isMax ? fmaxf(r, sm[i]) : r + sm[i];
        sm[16] = r;
    }
    __syncthreads();
    return sm[16];
}

// ---- Fused prologue kernel ----
// blocks 0..5   : per-(b,c) score softmax + pack p1/sm/p0s           (512 thr)
// blocks 6..21  : BEV box decode + area into g_p1v.w (16 x 512 = 8192 rows)
// blocks 22..58 : pass-through float4 copies (bbox_preds, pp_params)
#define BBOX_F4 14336   // 2*28*1024 /4
#define PP_F4   4608    // 2*9*1024  /4
__global__ __launch_bounds__(512) void prologue_kernel(
    const float* __restrict__ scores, const float* __restrict__ pp,
    const float* __restrict__ decoded,
    const float4* __restrict__ bboxv, const float4* __restrict__ ppv,
    float4* __restrict__ out_bbox, float4* __restrict__ out_pp)
{
    int blk = blockIdx.x, tid = threadIdx.x;

    if (blk >= 22) {                       // pass-through copies
        int idx = (blk - 22) * 512 + tid;  // 0..18943
        if (idx < BBOX_F4) out_bbox[idx] = bboxv[idx];
        else               out_pp[idx - BBOX_F4] = ppv[idx - BBOX_F4];
        return;
    }
    if (blk >= 6) {                        // box decode + area
        int idx = (blk - 6) * 512 + tid;   // 0..8191
        const float* d = decoded + (size_t)idx * 7;
        float x = d[0], y = d[1], d0 = d[3], d1 = d[4], rot = d[6];
        const float PIf  = 3.14159265358979323846f;
        const float PI4f = 0.78539816339744830962f;
        float k = floorf(rot / PIf + 0.5f);
        float normed = fabsf(rot - k * PIf);
        bool sw = normed > PI4f;
        float w = sw ? d1 : d0;
        float h = sw ? d0 : d1;
        g_box[idx] = make_float4(x - 0.5f * w, y - 0.5f * h, x + 0.5f * w, y + 0.5f * h);
        ((float*)&g_p1v[idx])[3] = w * h;   // area (disjoint from prep's .x/.y/.z writes)
        return;
    }

    // prep: one block per (b,c)
    __shared__ float sm[17];
    int b = blk / Cc, c = blk % Cc;
    const float* sb = scores + b * (Ac * Cc * HWc);
    const float* pb = pp     + b * (Cc * 3 * HWc);
    float scv[8];
    float mx = -1e30f;
    #pragma unroll
    for (int k = 0; k < 8; k++) {
        int n = (k << 9) + tid;
        int hw = n >> 2, a = n & 3;
        float sc = sb[(a * Cc + c) * HWc + hw];
        float p0 = pb[(c * 3 + 0) * HWc + hw];
        float p1 = pb[(c * 3 + 1) * HWc + hw];
        ((float*)&g_p0s[b * Nc + n])[c] = p0 * LOG2E;
        ((float*)&g_p1v[b * Nc + n])[c] = p1;
        scv[k] = sc;
        mx = fmaxf(mx, sc);
    }
    mx = blockReduce(mx, true, sm);
    float ev[8], se = 0.f;
    #pragma unroll
    for (int k = 0; k < 8; k++) { ev[k] = expf(scv[k] - mx); se += ev[k]; }
    se = blockReduce(se, false, sm);
    float inv = 1.0f / se;
    #pragma unroll
    for (int k = 0; k < 8; k++) {
        int n = (k << 9) + tid;
        ((float*)&g_smv[b * Nc + n])[c] = ev[k] * inv;
    }
}

// ---- Main kernel ----
// Block = 128 thr = 4 warps: warps {0,1} -> row 2*blk, warps {2,3} -> row 2*blk+1.
// Within a row pair of warps, each handles one half of j (2048 each) for finer
// wave granularity; partial (lsum,acc) combined via smem.
__global__ __launch_bounds__(128, 9) void main_kernel(float* __restrict__ out) {
    int wid  = threadIdx.x >> 5, lane = threadIdx.x & 31;
    int row  = blockIdx.x * 2 + (wid >> 1);   // 0..8191
    int jh   = wid & 1;                       // j half
    int b    = row >> 12;
    int i    = row & (Nc - 1);

    const float4* __restrict__ boxB = g_box + b * Nc;
    const float4* __restrict__ p1B  = g_p1v + b * Nc;
    const float4* __restrict__ smB  = g_smv + b * Nc;

    float4 bb = boxB[i];
    float  ai = __ldg(&((const float*)(p1B + i))[3]);  // area of row box
    float4 p0 = g_p0s[b * Nc + i];                     // p0*log2e per class

    float ls0 = 0.f, ls1 = 0.f, ls2 = 0.f;
    float ac0 = 0.f, ac1 = 0.f, ac2 = 0.f;

    int j0 = (jh << 11) + lane;                        // 0/2048 + lane
    #pragma unroll 4
    for (int jj = 0; jj < 64; jj++) {
        int j = j0 + (jj << 5);
        float4 bj  = __ldg(boxB + j);
        float4 p1j = __ldg(p1B + j);                   // .w = area_j
        float4 smj = __ldg(smB + j);
        float lx = fmaxf(bb.x, bj.x);
        float ly = fmaxf(bb.y, bj.y);
        float rx = fminf(bb.z, bj.z);
        float ry = fminf(bb.w, bj.w);
        float w  = fmaxf(rx - lx, 0.f);
        float h  = fmaxf(ry - ly, 0.f);
        float inter = w * h;
        float uni   = (ai + p1j.w) - inter;            // union >= 0.25 always
        float rcu   = __fdividef(LOG2E, uni);          // MUFU rcp + mul
        float t0 = p0.x * p1j.x;                       // log2-domain rank-1 term
        float t1 = p0.y * p1j.y;
        float t2 = p0.z * p1j.z;
        float e0 = ex2f(fmaf(inter, rcu, t0));
        float e1 = ex2f(fmaf(inter, rcu, t1));
        float e2 = ex2f(fmaf(inter, rcu, t2));
        ls0 += e0;  ac0 = fmaf(e0, smj.x, ac0);
        ls1 += e1;  ac1 = fmaf(e1, smj.y, ac1);
        ls2 += e2;  ac2 = fmaf(e2, smj.z, ac2);
    }

    ls0 = warpSum(ls0); ls1 = warpSum(ls1); ls2 = warpSum(ls2);
    ac0 = warpSum(ac0); ac1 = warpSum(ac1); ac2 = warpSum(ac2);

    __shared__ float red[4][6];
    if (lane == 0) {
        red[wid][0] = ls0; red[wid][1] = ls1; red[wid][2] = ls2;
        red[wid][3] = ac0; red[wid][4] = ac1; red[wid][5] = ac2;
    }
    __syncthreads();
    if ((wid & 1) == 0 && lane < 3) {
        float lsum = red[wid][lane]     + red[wid + 1][lane];
        float acc  = red[wid][lane + 3] + red[wid + 1][lane + 3];
        int a = i & 3, hw = i >> 2;
        out[b * (Ac * Cc * HWc) + (a * Cc + lane) * HWc + hw] = acc / lsum;
    }
}

extern "C" void kernel_launch(void* const* d_in, const int* in_sizes, int n_in,
                              void* d_out, int out_size) {
    const float* scores  = (const float*)d_in[0];  // (2,12,32,32)
    const float* bbox    = (const float*)d_in[1];  // (2,28,32,32)
    const float* pp      = (const float*)d_in[2];  // (2,9,32,32)
    const float* decoded = (const float*)d_in[3];  // (2,4096,7)
    float* out = (float*)d_out;

    float4* out_bbox = (float4*)(out + Bc * Ac * Cc * HWc);
    float4* out_pp   = (float4*)(out + Bc * Ac * Cc * HWc + Bc * Ac * 7 * HWc);

    // 6 prep + 16 boxes + 37 copy = 59 blocks
    prologue_kernel<<<59, 512>>>(scores, pp, decoded,
                                 (const float4*)bbox, (const float4*)pp,
                                 out_bbox, out_pp);

    // 8192 rows, 2 rows per block -> 4096 blocks
    main_kernel<<<(Bc * Nc) / 2, 128>>>(out);
}

// round 8
// speedup vs baseline: 1.3491x; 1.3491x over previous
#include <cuda_runtime.h>
#include <math.h>

// Problem constants
#define Bc   2
#define Ac   4
#define Cc   3
#define HWc  1024
#define Nc   4096              // H*W*A
#define BNc  (Bc*Nc)           // 8192 rows
#define LOG2E 1.4426950408889634f

#define JCH  16                // j chunks per row
#define JPW  (Nc/JCH)          // 256 j per warp

// Scratch (device globals — no allocation allowed)
__device__ float4 g_box[BNc];     // BEV boxes (x1,y1,x2,y2)
__device__ float4 g_p1v[BNc];     // p1 per class in .x/.y/.z ; .w = box area
__device__ float4 g_smv[BNc];     // softmaxed score per class in .x/.y/.z
__device__ float4 g_p0s[BNc];     // p0*log2e per class in .x/.y/.z
__device__ float4 g_part[JCH*BNc*2]; // partials: per (chunk,row): {ls0,ls1,ls2,ac0},{ac1,ac2,-,-}

__device__ __forceinline__ float ex2f(float x) {
    float y; asm("ex2.approx.f32 %0, %1;" : "=f"(y) : "f"(x)); return y;
}
__device__ __forceinline__ float warpMax(float v) {
    #pragma unroll
    for (int o = 16; o; o >>= 1) v = fmaxf(v, __shfl_xor_sync(0xffffffffu, v, o));
    return v;
}
__device__ __forceinline__ float warpSum(float v) {
    #pragma unroll
    for (int o = 16; o; o >>= 1) v += __shfl_xor_sync(0xffffffffu, v, o);
    return v;
}
__device__ float blockReduce(float v, bool isMax, float* sm) {
    int tid = threadIdx.x, lane = tid & 31, w = tid >> 5;
    v = isMax ? warpMax(v) : warpSum(v);
    __syncthreads();
    if (lane == 0) sm[w] = v;
    __syncthreads();
    if (tid == 0) {
        float r = sm[0];
        int nw = blockDim.x >> 5;
        for (int i = 1; i < nw; i++) r = isMax ? fmaxf(r, sm[i]) : r + sm[i];
        sm[16] = r;
    }
    __syncthreads();
    return sm[16];
}

// ---- Fused prologue kernel ----
// blocks 0..5   : per-(b,c) score softmax + pack p1/sm/p0s           (512 thr)
// blocks 6..21  : BEV box decode + area into g_p1v.w (16 x 512 = 8192 rows)
// blocks 22..58 : pass-through float4 copies (bbox_preds, pp_params)
#define BBOX_F4 14336   // 2*28*1024 /4
#define PP_F4   4608    // 2*9*1024  /4
__global__ __launch_bounds__(512) void prologue_kernel(
    const float* __restrict__ scores, const float* __restrict__ pp,
    const float* __restrict__ decoded,
    const float4* __restrict__ bboxv, const float4* __restrict__ ppv,
    float4* __restrict__ out_bbox, float4* __restrict__ out_pp)
{
    int blk = blockIdx.x, tid = threadIdx.x;

    if (blk >= 22) {                       // pass-through copies
        int idx = (blk - 22) * 512 + tid;  // 0..18943
        if (idx < BBOX_F4) out_bbox[idx] = bboxv[idx];
        else               out_pp[idx - BBOX_F4] = ppv[idx - BBOX_F4];
        return;
    }
    if (blk >= 6) {                        // box decode + area
        int idx = (blk - 6) * 512 + tid;   // 0..8191
        const float* d = decoded + (size_t)idx * 7;
        float x = d[0], y = d[1], d0 = d[3], d1 = d[4], rot = d[6];
        const float PIf  = 3.14159265358979323846f;
        const float PI4f = 0.78539816339744830962f;
        float k = floorf(rot / PIf + 0.5f);
        float normed = fabsf(rot - k * PIf);
        bool sw = normed > PI4f;
        float w = sw ? d1 : d0;
        float h = sw ? d0 : d1;
        g_box[idx] = make_float4(x - 0.5f * w, y - 0.5f * h, x + 0.5f * w, y + 0.5f * h);
        ((float*)&g_p1v[idx])[3] = w * h;   // area (disjoint from prep's .x/.y/.z writes)
        return;
    }

    // prep: one block per (b,c)
    __shared__ float sm[17];
    int b = blk / Cc, c = blk % Cc;
    const float* sb = scores + b * (Ac * Cc * HWc);
    const float* pb = pp     + b * (Cc * 3 * HWc);
    float scv[8];
    float mx = -1e30f;
    #pragma unroll
    for (int k = 0; k < 8; k++) {
        int n = (k << 9) + tid;
        int hw = n >> 2, a = n & 3;
        float sc = sb[(a * Cc + c) * HWc + hw];
        float p0 = pb[(c * 3 + 0) * HWc + hw];
        float p1 = pb[(c * 3 + 1) * HWc + hw];
        ((float*)&g_p0s[b * Nc + n])[c] = p0 * LOG2E;
        ((float*)&g_p1v[b * Nc + n])[c] = p1;
        scv[k] = sc;
        mx = fmaxf(mx, sc);
    }
    mx = blockReduce(mx, true, sm);
    float ev[8], se = 0.f;
    #pragma unroll
    for (int k = 0; k < 8; k++) { ev[k] = expf(scv[k] - mx); se += ev[k]; }
    se = blockReduce(se, false, sm);
    float inv = 1.0f / se;
    #pragma unroll
    for (int k = 0; k < 8; k++) {
        int n = (k << 9) + tid;
        ((float*)&g_smv[b * Nc + n])[c] = ev[k] * inv;
    }
}

// ---- Main kernel: lanes over ROWS, j warp-uniform (broadcast loads) ----
// Warp = 32 consecutive rows x 256-j chunk. Each j-iter: 3 uniform LDG.128
// (~3 L1 wavefronts) serve 32 pairs. Partials to g_part (deterministic).
// Grid: 256 rowgroups x 4 jquads = 1024 blocks; 4 warps/block = 16 chunks/row.
__global__ __launch_bounds__(128) void main_kernel() {
    int wid  = threadIdx.x >> 5, lane = threadIdx.x & 31;
    int rg   = blockIdx.x >> 2;                 // 0..255 row group
    int jc   = ((blockIdx.x & 3) << 2) | wid;   // 0..15 j chunk
    int row  = (rg << 5) + lane;                // 0..8191
    int b    = row >> 12;
    int i    = row & (Nc - 1);

    const float4* __restrict__ boxB = g_box + b * Nc;
    const float4* __restrict__ p1B  = g_p1v + b * Nc;
    const float4* __restrict__ smB  = g_smv + b * Nc;

    float4 bb = boxB[i];                        // this lane's row box
    float4 pr = p1B[i];                         // .w = row area
    float4 p0 = g_p0s[b * Nc + i];              // p0*log2e per class
    float  ai = pr.w;

    float ls0 = 0.f, ls1 = 0.f, ls2 = 0.f;
    float ac0 = 0.f, ac1 = 0.f, ac2 = 0.f;

    int jbase = jc * JPW;
    #pragma unroll 4
    for (int jj = 0; jj < JPW; jj++) {
        int j = jbase + jj;                     // warp-uniform
        float4 bj  = __ldg(boxB + j);           // broadcast: 1-2 wavefronts
        float4 p1j = __ldg(p1B + j);
        float4 smj = __ldg(smB + j);
        float lx = fmaxf(bb.x, bj.x);
        float ly = fmaxf(bb.y, bj.y);
        float rx = fminf(bb.z, bj.z);
        float ry = fminf(bb.w, bj.w);
        float w  = fmaxf(rx - lx, 0.f);
        float h  = fmaxf(ry - ly, 0.f);
        float inter = w * h;
        float uni   = (ai + p1j.w) - inter;     // union >= 0.25 always
        float rcu   = __fdividef(LOG2E, uni);   // MUFU rcp + mul
        float t0 = p0.x * p1j.x;                // log2-domain rank-1 term
        float t1 = p0.y * p1j.y;
        float t2 = p0.z * p1j.z;
        float e0 = ex2f(fmaf(inter, rcu, t0));
        float e1 = ex2f(fmaf(inter, rcu, t1));
        float e2 = ex2f(fmaf(inter, rcu, t2));
        ls0 += e0;  ac0 = fmaf(e0, smj.x, ac0);
        ls1 += e1;  ac1 = fmaf(e1, smj.y, ac1);
        ls2 += e2;  ac2 = fmaf(e2, smj.z, ac2);
    }

    size_t p = ((size_t)jc * BNc + row) * 2;
    g_part[p]     = make_float4(ls0, ls1, ls2, ac0);
    g_part[p + 1] = make_float4(ac1, ac2, 0.f, 0.f);
}

// ---- Epilogue: reduce 16 chunks per row, divide, scatter to output layout ----
__global__ __launch_bounds__(256) void epilogue_kernel(float* __restrict__ out) {
    int row = blockIdx.x * 256 + threadIdx.x;   // 0..8191
    int b = row >> 12, i = row & (Nc - 1);
    float ls0 = 0.f, ls1 = 0.f, ls2 = 0.f;
    float ac0 = 0.f, ac1 = 0.f, ac2 = 0.f;
    #pragma unroll
    for (int jc = 0; jc < JCH; jc++) {
        size_t p = ((size_t)jc * BNc + row) * 2;
        float4 u = g_part[p];
        float4 v = g_part[p + 1];
        ls0 += u.x; ls1 += u.y; ls2 += u.z;
        ac0 += u.w; ac1 += v.x; ac2 += v.y;
    }
    int a = i & 3, hw = i >> 2;
    float* ob = out + b * (Ac * Cc * HWc);
    ob[(a * Cc + 0) * HWc + hw] = ac0 / ls0;
    ob[(a * Cc + 1) * HWc + hw] = ac1 / ls1;
    ob[(a * Cc + 2) * HWc + hw] = ac2 / ls2;
}

extern "C" void kernel_launch(void* const* d_in, const int* in_sizes, int n_in,
                              void* d_out, int out_size) {
    const float* scores  = (const float*)d_in[0];  // (2,12,32,32)
    const float* bbox    = (const float*)d_in[1];  // (2,28,32,32)
    const float* pp      = (const float*)d_in[2];  // (2,9,32,32)
    const float* decoded = (const float*)d_in[3];  // (2,4096,7)
    float* out = (float*)d_out;

    float4* out_bbox = (float4*)(out + Bc * Ac * Cc * HWc);
    float4* out_pp   = (float4*)(out + Bc * Ac * Cc * HWc + Bc * Ac * 7 * HWc);

    // 6 prep + 16 boxes + 37 copy = 59 blocks
    prologue_kernel<<<59, 512>>>(scores, pp, decoded,
                                 (const float4*)bbox, (const float4*)pp,
                                 out_bbox, out_pp);

    // 256 rowgroups x 4 jquad-blocks (4 warps each -> 16 chunks) = 1024 blocks
    main_kernel<<<1024, 128>>>();

    // 8192 rows
    epilogue_kernel<<<BNc / 256, 256>>>(out);
}

// round 9
// speedup vs baseline: 1.5516x; 1.1501x over previous
#include <cuda_runtime.h>
#include <math.h>

// Problem constants
#define Bc   2
#define Ac   4
#define Cc   3
#define HWc  1024
#define Nc   4096              // H*W*A
#define BNc  (Bc*Nc)           // 8192 rows
#define LOG2E 1.4426950408889634f

#define JCH  32                // j chunks per batch
#define JPW  128               // j per chunk

// Scratch (device globals — no allocation allowed)
__device__ float4 g_box[BNc];       // BEV boxes (x1,y1,x2,y2)
__device__ float4 g_p1v[BNc];       // p1 per class in .x/.y/.z ; .w = box area
__device__ float4 g_smv[BNc];       // softmaxed score per class in .x/.y/.z
__device__ float4 g_p0s[BNc];       // p0*log2e per class in .x/.y/.z
__device__ float4 g_part[JCH*BNc*2];// partials per (chunk,row): {ls0,ls1,ls2,ac0},{ac1,ac2,-,-}

__device__ __forceinline__ float ex2f(float x) {
    float y; asm("ex2.approx.f32 %0, %1;" : "=f"(y) : "f"(x)); return y;
}
__device__ __forceinline__ float warpMax(float v) {
    #pragma unroll
    for (int o = 16; o; o >>= 1) v = fmaxf(v, __shfl_xor_sync(0xffffffffu, v, o));
    return v;
}
__device__ __forceinline__ float warpSum(float v) {
    #pragma unroll
    for (int o = 16; o; o >>= 1) v += __shfl_xor_sync(0xffffffffu, v, o);
    return v;
}
__device__ float blockReduce(float v, bool isMax, float* sm) {
    int tid = threadIdx.x, lane = tid & 31, w = tid >> 5;
    v = isMax ? warpMax(v) : warpSum(v);
    __syncthreads();
    if (lane == 0) sm[w] = v;
    __syncthreads();
    if (tid == 0) {
        float r = sm[0];
        int nw = blockDim.x >> 5;
        for (int i = 1; i < nw; i++) r = isMax ? fmaxf(r, sm[i]) : r + sm[i];
        sm[16] = r;
    }
    __syncthreads();
    return sm[16];
}

// ---- Prologue: prep (6 blocks) + box decode (16 blocks). Copies moved out. ----
__global__ __launch_bounds__(512) void prologue_kernel(
    const float* __restrict__ scores, const float* __restrict__ pp,
    const float* __restrict__ decoded)
{
    int blk = blockIdx.x, tid = threadIdx.x;

    if (blk >= 6) {                        // box decode + area
        int idx = (blk - 6) * 512 + tid;   // 0..8191
        const float* d = decoded + (size_t)idx * 7;
        float x = d[0], y = d[1], d0 = d[3], d1 = d[4], rot = d[6];
        const float PIf  = 3.14159265358979323846f;
        const float PI4f = 0.78539816339744830962f;
        float k = floorf(rot / PIf + 0.5f);
        float normed = fabsf(rot - k * PIf);
        bool sw = normed > PI4f;
        float w = sw ? d1 : d0;
        float h = sw ? d0 : d1;
        g_box[idx] = make_float4(x - 0.5f * w, y - 0.5f * h, x + 0.5f * w, y + 0.5f * h);
        ((float*)&g_p1v[idx])[3] = w * h;   // area (disjoint bytes from prep writes)
        return;
    }

    // prep: one block per (b,c)
    __shared__ float sm[17];
    int b = blk / Cc, c = blk % Cc;
    const float* sb = scores + b * (Ac * Cc * HWc);
    const float* pb = pp     + b * (Cc * 3 * HWc);
    float scv[8];
    float mx = -1e30f;
    #pragma unroll
    for (int k = 0; k < 8; k++) {
        int n = (k << 9) + tid;
        int hw = n >> 2, a = n & 3;
        float sc = sb[(a * Cc + c) * HWc + hw];
        float p0 = pb[(c * 3 + 0) * HWc + hw];
        float p1 = pb[(c * 3 + 1) * HWc + hw];
        ((float*)&g_p0s[b * Nc + n])[c] = p0 * LOG2E;
        ((float*)&g_p1v[b * Nc + n])[c] = p1;
        scv[k] = sc;
        mx = fmaxf(mx, sc);
    }
    mx = blockReduce(mx, true, sm);
    float ev[8], se = 0.f;
    #pragma unroll
    for (int k = 0; k < 8; k++) { ev[k] = expf(scv[k] - mx); se += ev[k]; }
    se = blockReduce(se, false, sm);
    float inv = 1.0f / se;
    #pragma unroll
    for (int k = 0; k < 8; k++) {
        int n = (k << 9) + tid;
        ((float*)&g_smv[b * Nc + n])[c] = ev[k] * inv;
    }
}

// ---- Main: lanes = rows, j-tile staged in SMEM (broadcast LDS reads) ----
// Block = 256 thr = 256 consecutive rows x one 128-j chunk.
// grid = 32 rowblocks x 32 chunks = 1024 blocks (chunk-major adjacency for L2).
__global__ __launch_bounds__(256) void main_kernel() {
    __shared__ float4 sj[JPW * 3];        // per j: {box, p1/area, sm} = 6KB

    int tid = threadIdx.x;
    int rb  = blockIdx.x & 31;            // row block 0..31
    int ch  = blockIdx.x >> 5;            // chunk 0..31
    int row = (rb << 8) + tid;            // 0..8191 (256 rows per block, same batch)
    int b   = row >> 12;
    int jb  = (b << 12) + ch * JPW;       // global j base for this batch+chunk

    // Stage j tile: 384 float4 by 256 threads
    {
        int k = tid;                       // first 256
        int f = k >> 7, e = k & 127;       // f in {0,1}: box, p1
        const float4* src = (f == 0) ? g_box : g_p1v;
        sj[e * 3 + f] = src[jb + e];
        if (tid < 128)                     // last 128: sm
            sj[tid * 3 + 2] = g_smv[jb + tid];
    }
    __syncthreads();

    // Row-resident state
    float4 bb = g_box[row];
    float4 p0 = g_p0s[row];               // p0*log2e per class
    float  ai = g_p1v[row].w;             // row box area

    float ls0 = 0.f, ls1 = 0.f, ls2 = 0.f;
    float ac0 = 0.f, ac1 = 0.f, ac2 = 0.f;

    #pragma unroll 4
    for (int jj = 0; jj < JPW; jj++) {
        float4 bj  = sj[jj * 3 + 0];      // LDS broadcast (conflict-free)
        float4 pj  = sj[jj * 3 + 1];      // .w = area_j
        float4 smj = sj[jj * 3 + 2];
        float lx = fmaxf(bb.x, bj.x);
        float ly = fmaxf(bb.y, bj.y);
        float rx = fminf(bb.z, bj.z);
        float ry = fminf(bb.w, bj.w);
        float w  = fmaxf(rx - lx, 0.f);
        float h  = fmaxf(ry - ly, 0.f);
        float inter = w * h;
        float uni   = (ai + pj.w) - inter;          // union >= 0.25 always
        float rcu   = __frcp_rn(uni);               // MUFU.RCP
        float iou   = inter * rcu;
        float t0 = p0.x * pj.x;                     // log2-domain rank-1 term
        float t1 = p0.y * pj.y;
        float t2 = p0.z * pj.z;
        float e0 = ex2f(fmaf(iou, LOG2E, t0));      // FFMA-imm
        float e1 = ex2f(fmaf(iou, LOG2E, t1));
        float e2 = ex2f(fmaf(iou, LOG2E, t2));
        ls0 += e0;  ac0 = fmaf(e0, smj.x, ac0);
        ls1 += e1;  ac1 = fmaf(e1, smj.y, ac1);
        ls2 += e2;  ac2 = fmaf(e2, smj.z, ac2);
    }

    size_t p = ((size_t)ch * BNc + row) * 2;
    g_part[p]     = make_float4(ls0, ls1, ls2, ac0);
    g_part[p + 1] = make_float4(ac1, ac2, 0.f, 0.f);
}

// ---- Epilogue: reduce 32 chunks/row + divide + scatter; plus pass-through copies ----
#define BBOX_F4 14336   // 2*28*1024 /4
#define PP_F4   4608    // 2*9*1024  /4
__global__ __launch_bounds__(256) void epilogue_kernel(
    float* __restrict__ out,
    const float4* __restrict__ bboxv, const float4* __restrict__ ppv,
    float4* __restrict__ out_bbox, float4* __restrict__ out_pp)
{
    int blk = blockIdx.x, tid = threadIdx.x;
    if (blk >= 32) {                      // copies: 74 blocks x 256 = 18944 f4
        int idx = (blk - 32) * 256 + tid;
        if (idx < BBOX_F4) out_bbox[idx] = bboxv[idx];
        else               out_pp[idx - BBOX_F4] = ppv[idx - BBOX_F4];
        return;
    }
    int row = blk * 256 + tid;            // 0..8191
    int b = row >> 12, i = row & (Nc - 1);
    float ls0 = 0.f, ls1 = 0.f, ls2 = 0.f;
    float ac0 = 0.f, ac1 = 0.f, ac2 = 0.f;
    #pragma unroll
    for (int jc = 0; jc < JCH; jc++) {
        size_t p = ((size_t)jc * BNc + row) * 2;
        float4 u = g_part[p];
        float4 v = g_part[p + 1];
        ls0 += u.x; ls1 += u.y; ls2 += u.z;
        ac0 += u.w; ac1 += v.x; ac2 += v.y;
    }
    int a = i & 3, hw = i >> 2;
    float* ob = out + b * (Ac * Cc * HWc);
    ob[(a * Cc + 0) * HWc + hw] = ac0 / ls0;
    ob[(a * Cc + 1) * HWc + hw] = ac1 / ls1;
    ob[(a * Cc + 2) * HWc + hw] = ac2 / ls2;
}

extern "C" void kernel_launch(void* const* d_in, const int* in_sizes, int n_in,
                              void* d_out, int out_size) {
    const float* scores  = (const float*)d_in[0];  // (2,12,32,32)
    const float* bbox    = (const float*)d_in[1];  // (2,28,32,32)
    const float* pp      = (const float*)d_in[2];  // (2,9,32,32)
    const float* decoded = (const float*)d_in[3];  // (2,4096,7)
    float* out = (float*)d_out;

    float4* out_bbox = (float4*)(out + Bc * Ac * Cc * HWc);
    float4* out_pp   = (float4*)(out + Bc * Ac * Cc * HWc + Bc * Ac * 7 * HWc);

    // 6 prep + 16 boxes = 22 blocks
    prologue_kernel<<<22, 512>>>(scores, pp, decoded);

    // 32 rowblocks x 32 chunks
    main_kernel<<<32 * JCH, 256>>>();

    // 32 reduce blocks + 74 copy blocks
    epilogue_kernel<<<106, 256>>>(out, (const float4*)bbox, (const float4*)pp,
                                  out_bbox, out_pp);
}

// round 10
// speedup vs baseline: 1.6615x; 1.0708x over previous
#include <cuda_runtime.h>
#include <math.h>

// Problem constants
#define Bc   2
#define Ac   4
#define Cc   3
#define HWc  1024
#define Nc   4096              // H*W*A
#define BNc  (Bc*Nc)           // 8192 rows
#define LOG2E 1.4426950408889634f

#define JCH  32                // j chunks per batch
#define JPW  128               // j per chunk

// Scratch (device globals — no allocation allowed)
__device__ float4 g_part[JCH*BNc*2]; // partials per (chunk,row): {ls0,ls1,ls2,ac0},{ac1,ac2,-,-}
__device__ float4 g_esum[Bc*JCH];    // per (b,chunk): sum of e_j per class (.x/.y/.z)

__device__ __forceinline__ float ex2f(float x) {
    float y; asm("ex2.approx.f32 %0, %1;" : "=f"(y) : "f"(x)); return y;
}
__device__ __forceinline__ float warpSum(float v) {
    #pragma unroll
    for (int o = 16; o; o >>= 1) v += __shfl_xor_sync(0xffffffffu, v, o);
    return v;
}

__device__ __forceinline__ float4 decode_box(const float* __restrict__ d, float& area) {
    float x = d[0], y = d[1], d0 = d[3], d1 = d[4], rot = d[6];
    const float PIf  = 3.14159265358979323846f;
    const float PI4f = 0.78539816339744830962f;
    float k = floorf(rot / PIf + 0.5f);
    float normed = fabsf(rot - k * PIf);
    bool sw = normed > PI4f;
    float w = sw ? d1 : d0;
    float h = sw ? d0 : d1;
    area = w * h;
    return make_float4(x - 0.5f * w, y - 0.5f * h, x + 0.5f * w, y + 0.5f * h);
}

// ---- Main kernel: fully self-staged; no prologue ----
// Blocks 0..1023: compute tiles. rb = row block (256 rows), ch = j chunk (128 j).
// Each block stages its j-tile (boxes decoded from `decoded`, e=exp(score), p1)
// into SMEM, then every thread runs its row against the tile.
// Blocks 1024..1097: pass-through copies (fill the tail wave).
#define BBOX_F4 14336   // 2*28*1024 /4
#define PP_F4   4608    // 2*9*1024  /4
__global__ __launch_bounds__(256) void main_kernel(
    const float* __restrict__ scores, const float* __restrict__ pp,
    const float* __restrict__ decoded,
    const float4* __restrict__ bboxv, const float4* __restrict__ ppv,
    float4* __restrict__ out_bbox, float4* __restrict__ out_pp)
{
    int tid = threadIdx.x;

    if (blockIdx.x >= 32 * JCH) {            // copy blocks
        int idx = (blockIdx.x - 32 * JCH) * 256 + tid;
        if (idx < BBOX_F4) out_bbox[idx] = bboxv[idx];
        else               out_pp[idx - BBOX_F4] = ppv[idx - BBOX_F4];
        return;
    }

    __shared__ float4 sj[JPW * 3];           // per j: {box}, {p1x,p1y,p1z,area}, {e0,e1,e2,-}

    int rb  = blockIdx.x & 31;               // row block 0..31
    int ch  = blockIdx.x >> 5;               // chunk 0..31
    int row = (rb << 8) + tid;               // 0..8191 (single batch per block)
    int b   = row >> 12;
    int i   = row & (Nc - 1);

    const float* sb = scores + b * (Ac * Cc * HWc);
    const float* pb = pp     + b * (Cc * 3 * HWc);

    // Stage j tile (threads 0..127, one j each)
    if (tid < JPW) {
        int jg = (b << 12) + ch * JPW + tid; // global row index of j
        int jl = jg & (Nc - 1);
        float areaJ;
        float4 bj = decode_box(decoded + (size_t)jg * 7, areaJ);
        int hw = jl >> 2, a = jl & 3;
        float e0 = expf(sb[(a * Cc + 0) * HWc + hw]);   // unnormalized softmax numerator
        float e1 = expf(sb[(a * Cc + 1) * HWc + hw]);
        float e2 = expf(sb[(a * Cc + 2) * HWc + hw]);
        float p10 = pb[(0 * 3 + 1) * HWc + hw];
        float p11 = pb[(1 * 3 + 1) * HWc + hw];
        float p12 = pb[(2 * 3 + 1) * HWc + hw];
        sj[tid * 3 + 0] = bj;
        sj[tid * 3 + 1] = make_float4(p10, p11, p12, areaJ);
        sj[tid * 3 + 2] = make_float4(e0, e1, e2, 0.f);
    }
    __syncthreads();

    // Designated blocks publish per-chunk e-sums (for S_bc reconstruction)
    if (((rb & 15) == 0) && tid < 32) {
        float s0 = 0.f, s1 = 0.f, s2 = 0.f;
        #pragma unroll
        for (int k = 0; k < 4; k++) {
            float4 ev = sj[(tid + 32 * k) * 3 + 2];
            s0 += ev.x; s1 += ev.y; s2 += ev.z;
        }
        s0 = warpSum(s0); s1 = warpSum(s1); s2 = warpSum(s2);
        if (tid == 0) g_esum[b * JCH + ch] = make_float4(s0, s1, s2, 0.f);
    }

    // Row-resident state (each thread decodes its own row)
    int hwI = i >> 2;
    float ai;
    float4 bb = decode_box(decoded + (size_t)row * 7, ai);
    float p00 = pb[(0 * 3 + 0) * HWc + hwI] * LOG2E;
    float p01 = pb[(1 * 3 + 0) * HWc + hwI] * LOG2E;
    float p02 = pb[(2 * 3 + 0) * HWc + hwI] * LOG2E;

    float ls0 = 0.f, ls1 = 0.f, ls2 = 0.f;
    float ac0 = 0.f, ac1 = 0.f, ac2 = 0.f;

    #pragma unroll 4
    for (int jj = 0; jj < JPW; jj++) {
        float4 bj  = sj[jj * 3 + 0];         // LDS broadcast (conflict-free)
        float4 pj  = sj[jj * 3 + 1];         // .w = area_j
        float4 ej  = sj[jj * 3 + 2];
        float lx = fmaxf(bb.x, bj.x);
        float ly = fmaxf(bb.y, bj.y);
        float rx = fminf(bb.z, bj.z);
        float ry = fminf(bb.w, bj.w);
        float w  = fmaxf(rx - lx, 0.f);
        float h  = fmaxf(ry - ly, 0.f);
        float inter = w * h;
        float uni   = (ai + pj.w) - inter;   // union >= 0.25 always (dims >= 0.5)
        float rcu   = __frcp_rn(uni);        // MUFU.RCP
        float iou   = inter * rcu;
        float t0 = p00 * pj.x;               // log2-domain rank-1 term
        float t1 = p01 * pj.y;
        float t2 = p02 * pj.z;
        float e0 = ex2f(fmaf(iou, LOG2E, t0));
        float e1 = ex2f(fmaf(iou, LOG2E, t1));
        float e2 = ex2f(fmaf(iou, LOG2E, t2));
        ls0 += e0;  ac0 = fmaf(e0, ej.x, ac0);
        ls1 += e1;  ac1 = fmaf(e1, ej.y, ac1);
        ls2 += e2;  ac2 = fmaf(e2, ej.z, ac2);
    }

    size_t p = ((size_t)ch * BNc + row) * 2;
    g_part[p]     = make_float4(ls0, ls1, ls2, ac0);
    g_part[p + 1] = make_float4(ac1, ac2, 0.f, 0.f);
}

// ---- Epilogue: reduce 32 chunks/row, divide by (lsum * S_bc), scatter ----
__global__ __launch_bounds__(256) void epilogue_kernel(float* __restrict__ out) {
    int row = blockIdx.x * 256 + threadIdx.x;   // 0..8191
    int b = row >> 12, i = row & (Nc - 1);

    // S_bc per class (uniform loads, L1-broadcast)
    float S0 = 0.f, S1 = 0.f, S2 = 0.f;
    #pragma unroll
    for (int c2 = 0; c2 < JCH; c2++) {
        float4 es = g_esum[b * JCH + c2];
        S0 += es.x; S1 += es.y; S2 += es.z;
    }

    float ls0 = 0.f, ls1 = 0.f, ls2 = 0.f;
    float ac0 = 0.f, ac1 = 0.f, ac2 = 0.f;
    #pragma unroll
    for (int jc = 0; jc < JCH; jc++) {
        size_t p = ((size_t)jc * BNc + row) * 2;
        float4 u = g_part[p];
        float4 v = g_part[p + 1];
        ls0 += u.x; ls1 += u.y; ls2 += u.z;
        ac0 += u.w; ac1 += v.x; ac2 += v.y;
    }
    int a = i & 3, hw = i >> 2;
    float* ob = out + b * (Ac * Cc * HWc);
    ob[(a * Cc + 0) * HWc + hw] = ac0 / (ls0 * S0);
    ob[(a * Cc + 1) * HWc + hw] = ac1 / (ls1 * S1);
    ob[(a * Cc + 2) * HWc + hw] = ac2 / (ls2 * S2);
}

extern "C" void kernel_launch(void* const* d_in, const int* in_sizes, int n_in,
                              void* d_out, int out_size) {
    const float* scores  = (const float*)d_in[0];  // (2,12,32,32)
    const float* bbox    = (const float*)d_in[1];  // (2,28,32,32)
    const float* pp      = (const float*)d_in[2];  // (2,9,32,32)
    const float* decoded = (const float*)d_in[3];  // (2,4096,7)
    float* out = (float*)d_out;

    float4* out_bbox = (float4*)(out + Bc * Ac * Cc * HWc);
    float4* out_pp   = (float4*)(out + Bc * Ac * Cc * HWc + Bc * Ac * 7 * HWc);

    // 1024 compute tiles + 74 copy blocks
    main_kernel<<<32 * JCH + 74, 256>>>(scores, pp, decoded,
                                        (const float4*)bbox, (const float4*)pp,
                                        out_bbox, out_pp);

    // 8192 rows
    epilogue_kernel<<<BNc / 256, 256>>>(out);
}

// round 11
// speedup vs baseline: 1.7694x; 1.0649x over previous
#include <cuda_runtime.h>
#include <math.h>

// Problem constants
#define Bc   2
#define Ac   4
#define Cc   3
#define HWc  1024
#define Nc   4096              // H*W*A
#define BNc  (Bc*Nc)           // 8192 rows
#define LOG2E 1.4426950408889634f

#define JCH  32                // j chunks per batch
#define JPW  128               // j per chunk

// Scratch (device globals — no allocation allowed)
// Transposed layout: per (row, chunk): {ls0,ls1,ls2,ac0},{ac1,ac2,-,-}
// -> one row's 32 chunks are 1KB contiguous (coalesced warp-per-row epilogue).
__device__ float4 g_part[BNc*JCH*2];
__device__ float4 g_esum[Bc*JCH];    // per (b,chunk): sum of e_j per class (.x/.y/.z)

__device__ __forceinline__ float ex2f(float x) {
    float y; asm("ex2.approx.f32 %0, %1;" : "=f"(y) : "f"(x)); return y;
}
__device__ __forceinline__ float warpSum(float v) {
    #pragma unroll
    for (int o = 16; o; o >>= 1) v += __shfl_xor_sync(0xffffffffu, v, o);
    return v;
}

__device__ __forceinline__ float4 decode_box(const float* __restrict__ d, float& area) {
    float x = d[0], y = d[1], d0 = d[3], d1 = d[4], rot = d[6];
    const float PIf  = 3.14159265358979323846f;
    const float PI4f = 0.78539816339744830962f;
    float k = floorf(rot / PIf + 0.5f);
    float normed = fabsf(rot - k * PIf);
    bool sw = normed > PI4f;
    float w = sw ? d1 : d0;
    float h = sw ? d0 : d1;
    area = w * h;
    return make_float4(x - 0.5f * w, y - 0.5f * h, x + 0.5f * w, y + 0.5f * h);
}

// ---- Main kernel: fully self-staged; no prologue ----
// Blocks 0..1023: compute tiles. rb = row block (256 rows), ch = j chunk (128 j).
// Blocks 1024..1097: pass-through copies (tail filler).
#define BBOX_F4 14336   // 2*28*1024 /4
#define PP_F4   4608    // 2*9*1024  /4
__global__ __launch_bounds__(256) void main_kernel(
    const float* __restrict__ scores, const float* __restrict__ pp,
    const float* __restrict__ decoded,
    const float4* __restrict__ bboxv, const float4* __restrict__ ppv,
    float4* __restrict__ out_bbox, float4* __restrict__ out_pp)
{
    int tid = threadIdx.x;

    if (blockIdx.x >= 32 * JCH) {            // copy blocks
        int idx = (blockIdx.x - 32 * JCH) * 256 + tid;
        if (idx < BBOX_F4) out_bbox[idx] = bboxv[idx];
        else               out_pp[idx - BBOX_F4] = ppv[idx - BBOX_F4];
        return;
    }

    __shared__ float4 sj[JPW * 3];           // per j: {box}, {p1x,p1y,p1z,area}, {e0,e1,e2,-}

    int rb  = blockIdx.x & 31;               // row block 0..31
    int ch  = blockIdx.x >> 5;               // chunk 0..31
    int row = (rb << 8) + tid;               // 0..8191 (single batch per block)
    int b   = row >> 12;
    int i   = row & (Nc - 1);

    const float* sb = scores + b * (Ac * Cc * HWc);
    const float* pb = pp     + b * (Cc * 3 * HWc);

    // Stage j tile (threads 0..127, one j each)
    if (tid < JPW) {
        int jg = (b << 12) + ch * JPW + tid; // global row index of j
        int jl = jg & (Nc - 1);
        float areaJ;
        float4 bj = decode_box(decoded + (size_t)jg * 7, areaJ);
        int hw = jl >> 2, a = jl & 3;
        float e0 = expf(sb[(a * Cc + 0) * HWc + hw]);   // unnormalized softmax numerator
        float e1 = expf(sb[(a * Cc + 1) * HWc + hw]);
        float e2 = expf(sb[(a * Cc + 2) * HWc + hw]);
        float p10 = pb[(0 * 3 + 1) * HWc + hw];
        float p11 = pb[(1 * 3 + 1) * HWc + hw];
        float p12 = pb[(2 * 3 + 1) * HWc + hw];
        sj[tid * 3 + 0] = bj;
        sj[tid * 3 + 1] = make_float4(p10, p11, p12, areaJ);
        sj[tid * 3 + 2] = make_float4(e0, e1, e2, 0.f);
    }
    __syncthreads();

    // Designated blocks publish per-chunk e-sums (for S_bc reconstruction)
    if (((rb & 15) == 0) && tid < 32) {
        float s0 = 0.f, s1 = 0.f, s2 = 0.f;
        #pragma unroll
        for (int k = 0; k < 4; k++) {
            float4 ev = sj[(tid + 32 * k) * 3 + 2];
            s0 += ev.x; s1 += ev.y; s2 += ev.z;
        }
        s0 = warpSum(s0); s1 = warpSum(s1); s2 = warpSum(s2);
        if (tid == 0) g_esum[b * JCH + ch] = make_float4(s0, s1, s2, 0.f);
    }

    // Row-resident state (each thread decodes its own row)
    int hwI = i >> 2;
    float ai;
    float4 bb = decode_box(decoded + (size_t)row * 7, ai);
    float p00 = pb[(0 * 3 + 0) * HWc + hwI] * LOG2E;
    float p01 = pb[(1 * 3 + 0) * HWc + hwI] * LOG2E;
    float p02 = pb[(2 * 3 + 0) * HWc + hwI] * LOG2E;

    float ls0 = 0.f, ls1 = 0.f, ls2 = 0.f;
    float ac0 = 0.f, ac1 = 0.f, ac2 = 0.f;

    #pragma unroll 8
    for (int jj = 0; jj < JPW; jj++) {
        float4 bj  = sj[jj * 3 + 0];         // LDS broadcast (conflict-free)
        float4 pj  = sj[jj * 3 + 1];         // .w = area_j
        float4 ej  = sj[jj * 3 + 2];
        float lx = fmaxf(bb.x, bj.x);
        float ly = fmaxf(bb.y, bj.y);
        float rx = fminf(bb.z, bj.z);
        float ry = fminf(bb.w, bj.w);
        float w  = fmaxf(rx - lx, 0.f);
        float h  = fmaxf(ry - ly, 0.f);
        float inter = w * h;
        float uni   = (ai + pj.w) - inter;   // union >= 0.25 always (dims >= 0.5)
        float rcu   = __frcp_rn(uni);        // MUFU.RCP
        float iou   = inter * rcu;
        float t0 = p00 * pj.x;               // log2-domain rank-1 term
        float t1 = p01 * pj.y;
        float t2 = p02 * pj.z;
        float e0 = ex2f(fmaf(iou, LOG2E, t0));
        float e1 = ex2f(fmaf(iou, LOG2E, t1));
        float e2 = ex2f(fmaf(iou, LOG2E, t2));
        ls0 += e0;  ac0 = fmaf(e0, ej.x, ac0);
        ls1 += e1;  ac1 = fmaf(e1, ej.y, ac1);
        ls2 += e2;  ac2 = fmaf(e2, ej.z, ac2);
    }

    // Transposed partials: row-major, 32B contiguous per (row,chunk)
    size_t p = ((size_t)row * JCH + ch) * 2;
    g_part[p]     = make_float4(ls0, ls1, ls2, ac0);
    g_part[p + 1] = make_float4(ac1, ac2, 0.f, 0.f);
}

// ---- Epilogue: warp per row, lane = chunk; fully coalesced 1KB row reads ----
__global__ __launch_bounds__(256) void epilogue_kernel(float* __restrict__ out) {
    int wid  = threadIdx.x >> 5, lane = threadIdx.x & 31;
    int row  = blockIdx.x * 8 + wid;            // 0..8191
    int b = row >> 12, i = row & (Nc - 1);

    size_t p = ((size_t)row * JCH + lane) * 2;
    float4 u = g_part[p];
    float4 v = g_part[p + 1];
    float4 es = g_esum[b * JCH + lane];

    float ls0 = warpSum(u.x), ls1 = warpSum(u.y), ls2 = warpSum(u.z);
    float ac0 = warpSum(u.w), ac1 = warpSum(v.x), ac2 = warpSum(v.y);
    float S0  = warpSum(es.x), S1 = warpSum(es.y), S2 = warpSum(es.z);

    if (lane == 0) {
        int a = i & 3, hw = i >> 2;
        float* ob = out + b * (Ac * Cc * HWc);
        ob[(a * Cc + 0) * HWc + hw] = ac0 / (ls0 * S0);
        ob[(a * Cc + 1) * HWc + hw] = ac1 / (ls1 * S1);
        ob[(a * Cc + 2) * HWc + hw] = ac2 / (ls2 * S2);
    }
}

extern "C" void kernel_launch(void* const* d_in, const int* in_sizes, int n_in,
                              void* d_out, int out_size) {
    const float* scores  = (const float*)d_in[0];  // (2,12,32,32)
    const float* bbox    = (const float*)d_in[1];  // (2,28,32,32)
    const float* pp      = (const float*)d_in[2];  // (2,9,32,32)
    const float* decoded = (const float*)d_in[3];  // (2,4096,7)
    float* out = (float*)d_out;

    float4* out_bbox = (float4*)(out + Bc * Ac * Cc * HWc);
    float4* out_pp   = (float4*)(out + Bc * Ac * Cc * HWc + Bc * Ac * 7 * HWc);

    // 1024 compute tiles + 74 copy blocks
    main_kernel<<<32 * JCH + 74, 256>>>(scores, pp, decoded,
                                        (const float4*)bbox, (const float4*)pp,
                                        out_bbox, out_pp);

    // 8192 rows, 8 warp-rows per block -> 1024 blocks
    epilogue_kernel<<<BNc / 8, 256>>>(out);
}

// round 12
// speedup vs baseline: 1.9797x; 1.1188x over previous
#include <cuda_runtime.h>
#include <math.h>

// Problem constants
#define Bc   2
#define Ac   4
#define Cc   3
#define HWc  1024
#define Nc   4096              // H*W*A
#define BNc  (Bc*Nc)           // 8192 rows
#define LOG2E 1.4426950408889634f

#define JCH  32                // j chunks per batch
#define JPW  128               // j per chunk (= 32 pixels x 4 anchors)

// Scratch (device globals — no allocation allowed)
// Per (row, chunk): {ls0,ls1,ls2,ac0},{ac1,ac2,-,-}; row-major (coalesced epilogue)
__device__ float4 g_part[BNc*JCH*2];
__device__ float4 g_esum[Bc*JCH];    // per (b,chunk): sum of e_j per class (.x/.y/.z)

__device__ __forceinline__ float ex2f(float x) {
    float y; asm("ex2.approx.f32 %0, %1;" : "=f"(y) : "f"(x)); return y;
}
__device__ __forceinline__ float warpSum(float v) {
    #pragma unroll
    for (int o = 16; o; o >>= 1) v += __shfl_xor_sync(0xffffffffu, v, o);
    return v;
}

__device__ __forceinline__ float4 decode_box(const float* __restrict__ d, float& area) {
    float x = d[0], y = d[1], d0 = d[3], d1 = d[4], rot = d[6];
    const float PIf  = 3.14159265358979323846f;
    const float PI4f = 0.78539816339744830962f;
    float k = floorf(rot / PIf + 0.5f);
    float normed = fabsf(rot - k * PIf);
    bool sw = normed > PI4f;
    float w = sw ? d1 : d0;
    float h = sw ? d0 : d1;
    area = w * h;
    return make_float4(x - 0.5f * w, y - 0.5f * h, x + 0.5f * w, y + 0.5f * h);
}

// ---- Main kernel: fully self-staged ----
// Blocks 0..1023: compute tiles (rb = 256-row block, ch = 128-j chunk).
// Blocks 1024..1097: pass-through copies (tail filler).
#define BBOX_F4 14336   // 2*28*1024 /4
#define PP_F4   4608    // 2*9*1024  /4
__global__ __launch_bounds__(256) void main_kernel(
    const float* __restrict__ scores, const float* __restrict__ pp,
    const float* __restrict__ decoded,
    const float4* __restrict__ bboxv, const float4* __restrict__ ppv,
    float4* __restrict__ out_bbox, float4* __restrict__ out_pp)
{
    int tid = threadIdx.x;

    if (blockIdx.x >= 32 * JCH) {            // copy blocks
        int idx = (blockIdx.x - 32 * JCH) * 256 + tid;
        if (idx < BBOX_F4) out_bbox[idx] = bboxv[idx];
        else               out_pp[idx - BBOX_F4] = ppv[idx - BBOX_F4];
        return;
    }

    __shared__ float4 sj[JPW * 3];           // per j: {box}, {p1x,p1y,p1z,area}, {e0,e1,e2,-}

    int rb  = blockIdx.x & 31;               // row block 0..31
    int ch  = blockIdx.x >> 5;               // chunk 0..31
    int row = (rb << 8) + tid;               // 0..8191 (single batch per block)
    int b   = row >> 12;
    int i   = row & (Nc - 1);

    const float* sb = scores + b * (Ac * Cc * HWc);
    const float* pb = pp     + b * (Cc * 3 * HWc);

    // Stage j tile (threads 0..127, one j each)
    if (tid < JPW) {
        int jg = (b << 12) + ch * JPW + tid; // global row index of j
        int jl = jg & (Nc - 1);
        float areaJ;
        float4 bj = decode_box(decoded + (size_t)jg * 7, areaJ);
        int hw = jl >> 2, a = jl & 3;
        float e0 = expf(sb[(a * Cc + 0) * HWc + hw]);   // unnormalized softmax numerator
        float e1 = expf(sb[(a * Cc + 1) * HWc + hw]);
        float e2 = expf(sb[(a * Cc + 2) * HWc + hw]);
        float p10 = pb[(0 * 3 + 1) * HWc + hw];
        float p11 = pb[(1 * 3 + 1) * HWc + hw];
        float p12 = pb[(2 * 3 + 1) * HWc + hw];
        sj[tid * 3 + 0] = bj;
        sj[tid * 3 + 1] = make_float4(p10, p11, p12, areaJ);
        sj[tid * 3 + 2] = make_float4(e0, e1, e2, 0.f);
    }
    __syncthreads();

    // Designated blocks publish per-chunk e-sums (for S_bc reconstruction)
    if (((rb & 15) == 0) && tid < 32) {
        float s0 = 0.f, s1 = 0.f, s2 = 0.f;
        #pragma unroll
        for (int k = 0; k < 4; k++) {
            float4 ev = sj[(tid + 32 * k) * 3 + 2];
            s0 += ev.x; s1 += ev.y; s2 += ev.z;
        }
        s0 = warpSum(s0); s1 = warpSum(s1); s2 = warpSum(s2);
        if (tid == 0) g_esum[b * JCH + ch] = make_float4(s0, s1, s2, 0.f);
    }

    // Row-resident state (each thread decodes its own row)
    int hwI = i >> 2;
    float ai;
    float4 bb = decode_box(decoded + (size_t)row * 7, ai);
    float p00 = pb[(0 * 3 + 0) * HWc + hwI] * LOG2E;
    float p01 = pb[(1 * 3 + 0) * HWc + hwI] * LOG2E;
    float p02 = pb[(2 * 3 + 0) * HWc + hwI] * LOG2E;

    float ls0 = 0.f, ls1 = 0.f, ls2 = 0.f;
    float ac0 = 0.f, ac1 = 0.f, ac2 = 0.f;

    // Pixel-factored inner loop: j's come as 32 pixels x 4 anchors; the rank-1
    // term exp2(p0*p1) depends only on the pixel -> 3 EX2 amortized over 4 j.
    #pragma unroll 4
    for (int px = 0; px < JPW / 4; px++) {
        int j4 = px << 2;
        float4 pj = sj[j4 * 3 + 1];          // p1 of this pixel (same for 4 anchors)
        float et0 = ex2f(p00 * pj.x);        // exp2(p0_c * p1_c * log2e)
        float et1 = ex2f(p01 * pj.y);
        float et2 = ex2f(p02 * pj.z);
        float siou = 0.f, w0 = 0.f, w1 = 0.f, w2 = 0.f;
        #pragma unroll
        for (int a = 0; a < 4; a++) {
            float4 bj = sj[(j4 + a) * 3 + 0];
            float aJ  = sj[(j4 + a) * 3 + 1].w;
            float4 ej = sj[(j4 + a) * 3 + 2];
            float lx = fmaxf(bb.x, bj.x);
            float ly = fmaxf(bb.y, bj.y);
            float rx = fminf(bb.z, bj.z);
            float ry = fminf(bb.w, bj.w);
            float w  = fmaxf(rx - lx, 0.f);
            float h  = fmaxf(ry - ly, 0.f);
            float inter = w * h * LOG2E;
            float uni   = (ai + aJ);                  // union = ai+aj-inter
            float rcu   = __frcp_rn(fmaf(w, -h, uni));// MUFU.RCP(union)
            float ei    = ex2f(inter * rcu);          // exp2(iou*log2e)
            siou += ei;
            w0 = fmaf(ei, ej.x, w0);
            w1 = fmaf(ei, ej.y, w1);
            w2 = fmaf(ei, ej.z, w2);
        }
        ls0 = fmaf(et0, siou, ls0);  ac0 = fmaf(et0, w0, ac0);
        ls1 = fmaf(et1, siou, ls1);  ac1 = fmaf(et1, w1, ac1);
        ls2 = fmaf(et2, siou, ls2);  ac2 = fmaf(et2, w2, ac2);
    }

    size_t p = ((size_t)row * JCH + ch) * 2;
    g_part[p]     = make_float4(ls0, ls1, ls2, ac0);
    g_part[p + 1] = make_float4(ac1, ac2, 0.f, 0.f);
}

// ---- Epilogue: warp per row, lane = chunk; fully coalesced 1KB row reads ----
__global__ __launch_bounds__(256) void epilogue_kernel(float* __restrict__ out) {
    int wid  = threadIdx.x >> 5, lane = threadIdx.x & 31;
    int row  = blockIdx.x * 8 + wid;            // 0..8191
    int b = row >> 12, i = row & (Nc - 1);

    size_t p = ((size_t)row * JCH + lane) * 2;
    float4 u = g_part[p];
    float4 v = g_part[p + 1];
    float4 es = g_esum[b * JCH + lane];

    float ls0 = warpSum(u.x), ls1 = warpSum(u.y), ls2 = warpSum(u.z);
    float ac0 = warpSum(u.w), ac1 = warpSum(v.x), ac2 = warpSum(v.y);
    float S0  = warpSum(es.x), S1 = warpSum(es.y), S2 = warpSum(es.z);

    if (lane == 0) {
        int a = i & 3, hw = i >> 2;
        float* ob = out + b * (Ac * Cc * HWc);
        ob[(a * Cc + 0) * HWc + hw] = ac0 / (ls0 * S0);
        ob[(a * Cc + 1) * HWc + hw] = ac1 / (ls1 * S1);
        ob[(a * Cc + 2) * HWc + hw] = ac2 / (ls2 * S2);
    }
}

extern "C" void kernel_launch(void* const* d_in, const int* in_sizes, int n_in,
                              void* d_out, int out_size) {
    const float* scores  = (const float*)d_in[0];  // (2,12,32,32)
    const float* bbox    = (const float*)d_in[1];  // (2,28,32,32)
    const float* pp      = (const float*)d_in[2];  // (2,9,32,32)
    const float* decoded = (const float*)d_in[3];  // (2,4096,7)
    float* out = (float*)d_out;

    float4* out_bbox = (float4*)(out + Bc * Ac * Cc * HWc);
    float4* out_pp   = (float4*)(out + Bc * Ac * Cc * HWc + Bc * Ac * 7 * HWc);

    // 1024 compute tiles + 74 copy blocks
    main_kernel<<<32 * JCH + 74, 256>>>(scores, pp, decoded,
                                        (const float4*)bbox, (const float4*)pp,
                                        out_bbox, out_pp);

    // 8192 rows, 8 warp-rows per block -> 1024 blocks
    epilogue_kernel<<<BNc / 8, 256>>>(out);
}